// round 11
// baseline (speedup 1.0000x reference)
#include <cuda_runtime.h>
#include <cuda_bf16.h>
#include <stdint.h>
#include <math.h>

// ---------------------------------------------------------------- constants
#define BATCH   2
#define NQ      16384
#define NATOMS  1024
#define KDIM    256
#define ODIM    256
#define NROWS   (BATCH * NQ)
#define OMEGA0  30.0f
#define EPSD    1e-4f

#define BM      128
#define BN      128
#define BKC     32
#define NCHUNK  (KDIM / BKC)     // 8
#define NTHREADS 512

// SMEM map (compact swizzled tiles: 32B rows, XOR bit7->bit4)
#define SL      4096             // one K16 slice (128 rows x 32B)
#define A_ST    16384
#define B_ST    16384
#define X_ST    16384            // fp32 X chunk 128x32 (128B rows, SW128)
#define OFF_A   0                // 2 stages: 0, 16384
#define OFF_B   32768            // 2 stages: 32768, 49152
#define OFF_X   65536            // 2 stages: 65536, 81920
#define SM_BYTES  98304
#define EPI_STRIDE 132

static __device__ __nv_bfloat16 g_Whi[ODIM * KDIM];
static __device__ __nv_bfloat16 g_Wlo[ODIM * KDIM];
static __device__ float         g_omega[NROWS];

#define WBLK    256              // W-split CTAs
#define OBLK    (NROWS / 64)     // omega CTAs (512)

// ---------------------------------------------------------------- helpers
__device__ __forceinline__ uint32_t smem_u32(const void* p) {
    uint32_t a;
    asm("{ .reg .u64 t; cvta.to.shared.u64 t, %1; cvt.u32.u64 %0, t; }" : "=r"(a) : "l"(p));
    return a;
}
__device__ __forceinline__ uint32_t swz(uint32_t o)   { return o ^ ((o >> 3) & 0x70); }
__device__ __forceinline__ uint32_t swz32(uint32_t o) { return o ^ ((o >> 3) & 0x10); }

__device__ __forceinline__ void sts_u4(uint32_t a, uint32_t x, uint32_t y,
                                       uint32_t z, uint32_t w) {
    asm volatile("st.shared.v4.b32 [%0], {%1,%2,%3,%4};" :: "r"(a), "r"(x), "r"(y), "r"(z), "r"(w));
}
__device__ __forceinline__ void cp16(uint32_t dst, const void* src) {
    asm volatile("cp.async.cg.shared.global [%0], [%1], 16;" :: "r"(dst), "l"(src));
}
#define CP_COMMIT() asm volatile("cp.async.commit_group;")
#define CP_WAIT0()  asm volatile("cp.async.wait_group 0;")

#define LDSM4(r, a) \
    asm volatile("ldmatrix.sync.aligned.m8n8.x4.shared.b16 {%0,%1,%2,%3}, [%4];" \
        : "=r"((r)[0]), "=r"((r)[1]), "=r"((r)[2]), "=r"((r)[3]) : "r"(a))

__device__ __forceinline__ void mma_bf16(float* c, const uint32_t* a,
                                         uint32_t b0, uint32_t b1) {
    asm volatile(
        "mma.sync.aligned.m16n8k16.row.col.f32.bf16.bf16.f32 "
        "{%0,%1,%2,%3}, {%4,%5,%6,%7}, {%8,%9}, {%0,%1,%2,%3};"
        : "+f"(c[0]), "+f"(c[1]), "+f"(c[2]), "+f"(c[3])
        : "r"(a[0]), "r"(a[1]), "r"(a[2]), "r"(a[3]), "r"(b0), "r"(b1));
}
__device__ __forceinline__ uint32_t packsplit(float x, float y, uint32_t& lo) {
    uint32_t h;
    asm("cvt.rn.bf16x2.f32 %0, %1, %2;" : "=r"(h) : "f"(y), "f"(x));
    float hx = __uint_as_float(h << 16);
    float hy = __uint_as_float(h & 0xffff0000u);
    float rx = x - hx, ry = y - hy;
    asm("cvt.rn.bf16x2.f32 %0, %1, %2;" : "=r"(lo) : "f"(ry), "f"(rx));
    return h;
}

// ---------------------------------------------------------------- prep: W split + omega
__global__ __launch_bounds__(256)
void prep_kernel(const float* __restrict__ W, const float* __restrict__ atoms,
                 const float* __restrict__ Q,
                 const float* __restrict__ fw1, const float* __restrict__ fb1,
                 const float* __restrict__ fw2, const float* __restrict__ fb2)
{
    const int b = blockIdx.x, tid = threadIdx.x;
    if (b < WBLK) {
        int i = b * 256 + tid;
        float w = W[i];
        __nv_bfloat16 h = __float2bfloat16(w);
        g_Whi[i] = h;
        g_Wlo[i] = __float2bfloat16(w - __bfloat162float(h));
        return;
    }
    // ---- omega: 64 queries per CTA, 4 threads per query ----
    __shared__ float4 sA[NATOMS];
    const int q0 = (b - WBLK) * 64;
    const int batch = (q0 >= NQ) ? 1 : 0;
    const float* ab = atoms + (size_t)batch * NATOMS * 3;
    for (int j = tid; j < NATOMS; j += 256) {
        float ax = ab[3*j], ay = ab[3*j+1], az = ab[3*j+2];
        sA[j] = make_float4(ax, ay, az, fmaf(ax, ax, fmaf(ay, ay, az*az)));
    }
    __syncthreads();

    const int qi = q0 + (tid >> 2);
    const int part = tid & 3;
    const float* qp = Q + (size_t)qi * 3;
    float qx = qp[0], qy = qp[1], qz = qp[2];
    float nqx = -2.f * qx, nqy = -2.f * qy, nqz = -2.f * qz;
    const float4* at = sA + part * 256;
    float m0 = 3.4e38f, m1 = 3.4e38f;
#pragma unroll 4
    for (int j = 0; j < 256; j += 2) {
        float4 a0 = at[j], a1 = at[j + 1];
        m0 = fminf(m0, fmaf(a0.x, nqx, fmaf(a0.y, nqy, fmaf(a0.z, nqz, a0.w))));
        m1 = fminf(m1, fmaf(a1.x, nqx, fmaf(a1.y, nqy, fmaf(a1.z, nqz, a1.w))));
    }
    float md = fminf(m0, m1);
    md = fminf(md, __shfl_xor_sync(0xffffffffu, md, 1));
    md = fminf(md, __shfl_xor_sync(0xffffffffu, md, 2));
    if (part == 0) {
        float qsq = fmaf(qx, qx, fmaf(qy, qy, qz * qz));
        float mind = sqrtf(fmaxf(md + qsq, EPSD));
        float ls = __ldg(fb2);
#pragma unroll
        for (int j = 0; j < 16; ++j) {
            float z = fmaf(__ldg(fw1 + 3*j), qx,
                      fmaf(__ldg(fw1 + 3*j + 1), qy,
                      fmaf(__ldg(fw1 + 3*j + 2), qz, __ldg(fb1 + j))));
            float sp = fmaxf(z, 0.0f) + log1pf(expf(-fabsf(z)));
            ls = fmaf(__ldg(fw2 + j), sp, ls);
        }
        ls = fminf(fmaxf(ls, 0.0f), 5.0f);
        g_omega[qi] = OMEGA0 * (1.0f + ls * expf(-mind));
    }
}

// ---------------------------------------------------------------- fused GEMM + sin
__global__ __launch_bounds__(NTHREADS, 2)
void siren_gemm(const float* __restrict__ X, const float* __restrict__ bias,
                float* __restrict__ out)
{
    extern __shared__ char sb[];
    const uint32_t sbase = smem_u32(sb);

    const int tid  = threadIdx.x;
    const int lane = tid & 31;
    const int wid  = tid >> 5;
    const int gRow0 = (blockIdx.x >> 1) * BM;
    const int gCol0 = (blockIdx.x & 1) * BN;

    const int warpM = (wid & 3) * 32;
    const int warpN = (wid >> 2) * 32;
    const int lr = lane >> 2;
    const int lc = (lane & 3) * 2;
    const int l7 = lane & 7, g = lane >> 3;
    const uint32_t aoff = swz32((uint32_t)((warpM + l7 + (g & 1) * 8) * 32 + ((g >> 1) & 1) * 16));
    const uint32_t boff = swz32((uint32_t)((warpN + l7 + (g >> 1) * 8) * 32 + (g & 1) * 16));

    // ---- loaders ------------------------------------------------------
    auto prefB = [&](int c) {
        const int n = tid >> 2, q = (tid >> 1) & 1, e = tid & 1;
        const uint32_t d0 = sbase + OFF_B + (uint32_t)(c & 1) * B_ST + q * 8192
                          + (swz32((uint32_t)(n * 32)) ^ (uint32_t)(e * 16));
        const int gs = (gCol0 + n) * KDIM + c * BKC + q * 16 + e * 8;
        cp16(d0,      g_Whi + gs);
        cp16(d0 + SL, g_Wlo + gs);
    };
    auto prefX = [&](int c) {
        const uint32_t base = sbase + OFF_X + (uint32_t)(c & 1) * X_ST;
        const float* src = X + (size_t)gRow0 * KDIM + c * BKC;
#pragma unroll
        for (int i = 0; i < 2; ++i) {
            int u = tid + i * NTHREADS;
            cp16(base + swz((uint32_t)u * 16), src + (size_t)(u >> 3) * KDIM + (u & 7) * 4);
        }
    };
    auto convertX = [&](int c) {
        const char* xs = sb + OFF_X + (uint32_t)(c & 1) * X_ST;
        const int r = tid >> 2, qd = tid & 3;
        const uint32_t xb = swz((uint32_t)(r * 128 + qd * 32));
        float4 v0 = *(const float4*)(xs + xb);
        float4 v1 = *(const float4*)(xs + (xb ^ 16));
        uint32_t h0, h1, h2, h3, l0, l1, l2, l3;
        h0 = packsplit(v0.x, v0.y, l0);  h1 = packsplit(v0.z, v0.w, l1);
        h2 = packsplit(v1.x, v1.y, l2);  h3 = packsplit(v1.z, v1.w, l3);
        const uint32_t ab = sbase + OFF_A + (uint32_t)(c & 1) * A_ST + (qd >> 1) * 8192
                          + (swz32((uint32_t)(r * 32)) ^ (uint32_t)((qd & 1) * 16));
        sts_u4(ab,      h0, h1, h2, h3);
        sts_u4(ab + SL, l0, l1, l2, l3);
    };

    // ---- prologue ----
    prefX(0);
    prefX(1);
    prefB(0);
    CP_COMMIT();
    CP_WAIT0();
    __syncthreads();
    convertX(0);                // published by iteration-0 barrier

    float acc[2][4][4];
#pragma unroll
    for (int i = 0; i < 2; ++i)
#pragma unroll
        for (int j = 0; j < 4; ++j)
#pragma unroll
            for (int k = 0; k < 4; ++k) acc[i][j][k] = 0.0f;

    // ---- main loop: wait -> barrier -> prefetch -> slice0 -> convert -> slice1
    // Race-free: every stage overwrite is issued only after a barrier that
    // postdates all readers of that stage.
#pragma unroll 1
    for (int c = 0; c < NCHUNK; ++c) {
        CP_WAIT0();             // group {X(c+1), B(c)} from iter c-1 landed
        __syncthreads();        // publish A(c) conversion + all prior reads
        if (c + 2 < NCHUNK) prefX(c + 2);
        if (c + 1 < NCHUNK) prefB(c + 1);
        CP_COMMIT();

        const uint32_t Ast = sbase + OFF_A + (uint32_t)(c & 1) * A_ST;
        const uint32_t Bst = sbase + OFF_B + (uint32_t)(c & 1) * B_ST;
#pragma unroll
        for (int s = 0; s < 2; ++s) {
            const uint32_t ab = Ast + s * 8192 + aoff;
            const uint32_t bb = Bst + s * 8192 + boff;
            uint32_t ah[2][4], al[2][4], bq[2][4];
            LDSM4(ah[0], ab);
            LDSM4(ah[1], ab + 512);
            LDSM4(al[0], ab + SL);
            LDSM4(al[1], ab + SL + 512);
            LDSM4(bq[0], bb);
            LDSM4(bq[1], bb + 512);
            // pass 1: hi*HI
#pragma unroll
            for (int mt = 0; mt < 2; ++mt)
#pragma unroll
                for (int p = 0; p < 2; ++p) {
                    mma_bf16(acc[mt][2*p],   ah[mt], bq[p][0], bq[p][1]);
                    mma_bf16(acc[mt][2*p+1], ah[mt], bq[p][2], bq[p][3]);
                }
            // pass 2: lo*HI
#pragma unroll
            for (int mt = 0; mt < 2; ++mt)
#pragma unroll
                for (int p = 0; p < 2; ++p) {
                    mma_bf16(acc[mt][2*p],   al[mt], bq[p][0], bq[p][1]);
                    mma_bf16(acc[mt][2*p+1], al[mt], bq[p][2], bq[p][3]);
                }
            // pass 3: hi*LO
            LDSM4(bq[0], bb + SL);
            LDSM4(bq[1], bb + SL + 512);
#pragma unroll
            for (int mt = 0; mt < 2; ++mt)
#pragma unroll
                for (int p = 0; p < 2; ++p) {
                    mma_bf16(acc[mt][2*p],   ah[mt], bq[p][0], bq[p][1]);
                    mma_bf16(acc[mt][2*p+1], ah[mt], bq[p][2], bq[p][3]);
                }
            // convert next chunk inside the MMA shadow (between slices)
            if (s == 0 && c + 1 < NCHUNK) convertX(c + 1);
        }
    }
    __syncthreads();            // all tile reads done; smem free

    // ---- epilogue: sin(omega*(acc+bias)) -> SMEM -> coalesced STG ----
    float* stg = (float*)sb;
#pragma unroll
    for (int mt = 0; mt < 2; ++mt) {
        int r0 = warpM + mt * 16 + lr;
        float o0 = __ldg(g_omega + gRow0 + r0);
        float o1 = __ldg(g_omega + gRow0 + r0 + 8);
#pragma unroll
        for (int nt = 0; nt < 4; ++nt) {
            int c0 = warpN + nt * 8 + lc;
            float b0 = __ldg(bias + gCol0 + c0), b1 = __ldg(bias + gCol0 + c0 + 1);
            float* a = acc[mt][nt];
            *(float2*)(stg + r0 * EPI_STRIDE + c0) =
                make_float2(__sinf(o0 * (a[0] + b0)), __sinf(o0 * (a[1] + b1)));
            *(float2*)(stg + (r0 + 8) * EPI_STRIDE + c0) =
                make_float2(__sinf(o1 * (a[2] + b0)), __sinf(o1 * (a[3] + b1)));
        }
    }
    __syncthreads();
#pragma unroll
    for (int i = 0; i < 8; ++i) {
        int lin = tid + i * NTHREADS;
        int rr = lin >> 5, c4 = (lin & 31) * 4;
        *(float4*)(out + (size_t)(gRow0 + rr) * ODIM + gCol0 + c4) =
            *(const float4*)(stg + rr * EPI_STRIDE + c4);
    }
}

// ---------------------------------------------------------------- launch
extern "C" void kernel_launch(void* const* d_in, const int* in_sizes, int n_in,
                              void* d_out, int out_size)
{
    const float* x     = (const float*)d_in[0];
    const float* q     = (const float*)d_in[1];
    const float* atoms = (const float*)d_in[2];
    const float* W     = (const float*)d_in[3];
    const float* bias  = (const float*)d_in[4];
    const float* fw1   = (const float*)d_in[5];
    const float* fb1   = (const float*)d_in[6];
    const float* fw2   = (const float*)d_in[7];
    const float* fb2   = (const float*)d_in[8];
    float* out = (float*)d_out;
    (void)in_sizes; (void)n_in; (void)out_size;

    cudaFuncSetAttribute(siren_gemm, cudaFuncAttributeMaxDynamicSharedMemorySize, SM_BYTES);

    prep_kernel<<<WBLK + OBLK, 256>>>(W, atoms, q, fw1, fb1, fw2, fb2);
    siren_gemm<<<(NROWS / BM) * (ODIM / BN), NTHREADS, SM_BYTES>>>(x, bias, out);
}

// round 12
// speedup vs baseline: 1.8863x; 1.8863x over previous
#include <cuda_runtime.h>
#include <cuda_bf16.h>
#include <stdint.h>
#include <math.h>

// ---------------------------------------------------------------- constants
#define BATCH   2
#define NQ      16384
#define NATOMS  1024
#define KDIM    256
#define ODIM    256
#define NROWS   (BATCH * NQ)
#define OMEGA0  30.0f
#define EPSD    1e-4f

#define BM      128
#define BN      128
#define BKC     32
#define NCHUNK  (KDIM / BKC)     // 8
#define NTHREADS 512

#define OMEGA_CTAS 128           // 256 queries each
#define GEMM_CTAS  ((NROWS / BM) * (ODIM / BN))   // 512

// SMEM map for GEMM path (compact swizzled tiles: 32B rows, XOR bit7->bit4)
#define SL      4096
#define A_ST    16384
#define B_ST    16384
#define X_ST    16384
#define OFF_A   0
#define OFF_B   32768
#define OFF_X   65536
#define SM_BYTES  98304
#define EPI_STRIDE 132
// omega path: 2 partitions x (512 float4 + 16B pad)
#define PAD_PART 8208

static __device__ __nv_bfloat16 g_Whi[ODIM * KDIM];
static __device__ __nv_bfloat16 g_Wlo[ODIM * KDIM];
static __device__ float         g_omega[NROWS];
static __device__ int           g_flag;

// ---------------------------------------------------------------- helpers
__device__ __forceinline__ uint32_t smem_u32(const void* p) {
    uint32_t a;
    asm("{ .reg .u64 t; cvta.to.shared.u64 t, %1; cvt.u32.u64 %0, t; }" : "=r"(a) : "l"(p));
    return a;
}
__device__ __forceinline__ uint32_t swz(uint32_t o)   { return o ^ ((o >> 3) & 0x70); }
__device__ __forceinline__ uint32_t swz32(uint32_t o) { return o ^ ((o >> 3) & 0x10); }

__device__ __forceinline__ void sts_u4(uint32_t a, uint32_t x, uint32_t y,
                                       uint32_t z, uint32_t w) {
    asm volatile("st.shared.v4.b32 [%0], {%1,%2,%3,%4};" :: "r"(a), "r"(x), "r"(y), "r"(z), "r"(w));
}
__device__ __forceinline__ void cp16(uint32_t dst, const void* src) {
    asm volatile("cp.async.cg.shared.global [%0], [%1], 16;" :: "r"(dst), "l"(src));
}
#define CP_COMMIT() asm volatile("cp.async.commit_group;")
#define CP_WAIT0()  asm volatile("cp.async.wait_group 0;")

#define LDSM4(r, a) \
    asm volatile("ldmatrix.sync.aligned.m8n8.x4.shared.b16 {%0,%1,%2,%3}, [%4];" \
        : "=r"((r)[0]), "=r"((r)[1]), "=r"((r)[2]), "=r"((r)[3]) : "r"(a))

__device__ __forceinline__ void mma_bf16(float* c, const uint32_t* a,
                                         uint32_t b0, uint32_t b1) {
    asm volatile(
        "mma.sync.aligned.m16n8k16.row.col.f32.bf16.bf16.f32 "
        "{%0,%1,%2,%3}, {%4,%5,%6,%7}, {%8,%9}, {%0,%1,%2,%3};"
        : "+f"(c[0]), "+f"(c[1]), "+f"(c[2]), "+f"(c[3])
        : "r"(a[0]), "r"(a[1]), "r"(a[2]), "r"(a[3]), "r"(b0), "r"(b1));
}
__device__ __forceinline__ uint32_t packsplit(float x, float y, uint32_t& lo) {
    uint32_t h;
    asm("cvt.rn.bf16x2.f32 %0, %1, %2;" : "=r"(h) : "f"(y), "f"(x));
    float hx = __uint_as_float(h << 16);
    float hy = __uint_as_float(h & 0xffff0000u);
    float rx = x - hx, ry = y - hy;
    asm("cvt.rn.bf16x2.f32 %0, %1, %2;" : "=r"(lo) : "f"(ry), "f"(rx));
    return h;
}

// ---------------------------------------------------------------- prep: W split + flag reset
__global__ __launch_bounds__(256)
void prep_w(const float* __restrict__ W)
{
    if (blockIdx.x == 0 && threadIdx.x == 0) g_flag = 0;
    int i = blockIdx.x * 256 + threadIdx.x;
    float w = W[i];
    __nv_bfloat16 h = __float2bfloat16(w);
    g_Whi[i] = h;
    g_Wlo[i] = __float2bfloat16(w - __bfloat162float(h));
}

// ---------------------------------------------------------------- main: omega CTAs + GEMM CTAs
__global__ __launch_bounds__(NTHREADS, 2)
void siren_main(const float* __restrict__ X, const float* __restrict__ Q,
                const float* __restrict__ atoms, const float* __restrict__ bias,
                const float* __restrict__ fw1, const float* __restrict__ fb1,
                const float* __restrict__ fw2, const float* __restrict__ fb2,
                float* __restrict__ out)
{
    extern __shared__ char sb[];
    const uint32_t sbase = smem_u32(sb);
    const int tid = threadIdx.x;

    // ================= omega CTAs (first wave) =================
    if (blockIdx.x < OMEGA_CTAS) {
        const int q0 = blockIdx.x * 256;
        const int batch = (q0 >= NQ) ? 1 : 0;
        const float* ab = atoms + (size_t)batch * NATOMS * 3;
        // load atoms into 2 padded partitions (bank-conflict-free scan)
        for (int j = tid; j < NATOMS; j += NTHREADS) {
            float ax = ab[3*j], ay = ab[3*j+1], az = ab[3*j+2];
            *(float4*)(sb + (j >> 9) * PAD_PART + (j & 511) * 16) =
                make_float4(ax, ay, az, fmaf(ax, ax, fmaf(ay, ay, az*az)));
        }
        __syncthreads();

        const int qi = q0 + (tid >> 1);
        const int part = tid & 1;
        const float* qp = Q + (size_t)qi * 3;
        float qx = qp[0], qy = qp[1], qz = qp[2];
        float nqx = -2.f * qx, nqy = -2.f * qy, nqz = -2.f * qz;
        const float4* at = (const float4*)(sb + part * PAD_PART);
        float m0 = 3.4e38f, m1 = 3.4e38f;
#pragma unroll 4
        for (int j = 0; j < 512; j += 2) {
            float4 a0 = at[j], a1 = at[j + 1];
            m0 = fminf(m0, fmaf(a0.x, nqx, fmaf(a0.y, nqy, fmaf(a0.z, nqz, a0.w))));
            m1 = fminf(m1, fmaf(a1.x, nqx, fmaf(a1.y, nqy, fmaf(a1.z, nqz, a1.w))));
        }
        float md = fminf(m0, m1);
        md = fminf(md, __shfl_xor_sync(0xffffffffu, md, 1));
        if (part == 0) {
            float qsq = fmaf(qx, qx, fmaf(qy, qy, qz * qz));
            float mind = sqrtf(fmaxf(md + qsq, EPSD));
            float ls = __ldg(fb2);
#pragma unroll
            for (int j = 0; j < 16; ++j) {
                float z = fmaf(__ldg(fw1 + 3*j), qx,
                          fmaf(__ldg(fw1 + 3*j + 1), qy,
                          fmaf(__ldg(fw1 + 3*j + 2), qz, __ldg(fb1 + j))));
                float sp = fmaxf(z, 0.0f) + log1pf(expf(-fabsf(z)));
                ls = fmaf(__ldg(fw2 + j), sp, ls);
            }
            ls = fminf(fmaxf(ls, 0.0f), 5.0f);
            g_omega[qi] = OMEGA0 * (1.0f + ls * expf(-mind));
        }
        __threadfence();
        __syncthreads();
        if (tid == 0) atomicAdd(&g_flag, 1);
        return;
    }

    // ================= GEMM CTAs =================
    const int bid = blockIdx.x - OMEGA_CTAS;
    const int lane = tid & 31;
    const int wid  = tid >> 5;
    const int gRow0 = (bid >> 1) * BM;
    const int gCol0 = (bid & 1) * BN;

    const int warpM = (wid & 3) * 32;
    const int warpN = (wid >> 2) * 32;
    const int lr = lane >> 2;
    const int lc = (lane & 3) * 2;
    const int l7 = lane & 7, g = lane >> 3;
    const uint32_t aoff = swz32((uint32_t)((warpM + l7 + (g & 1) * 8) * 32 + ((g >> 1) & 1) * 16));
    const uint32_t boff = swz32((uint32_t)((warpN + l7 + (g >> 1) * 8) * 32 + (g & 1) * 16));

    auto prefB = [&](int c) {
        const int n = tid >> 2, q = (tid >> 1) & 1, e = tid & 1;
        const uint32_t d0 = sbase + OFF_B + (uint32_t)(c & 1) * B_ST + q * 8192
                          + (swz32((uint32_t)(n * 32)) ^ (uint32_t)(e * 16));
        const int gs = (gCol0 + n) * KDIM + c * BKC + q * 16 + e * 8;
        cp16(d0,      g_Whi + gs);
        cp16(d0 + SL, g_Wlo + gs);
    };
    auto prefX = [&](int c) {
        const uint32_t base = sbase + OFF_X + (uint32_t)(c & 1) * X_ST;
        const float* src = X + (size_t)gRow0 * KDIM + c * BKC;
#pragma unroll
        for (int i = 0; i < 2; ++i) {
            int u = tid + i * NTHREADS;
            cp16(base + swz((uint32_t)u * 16), src + (size_t)(u >> 3) * KDIM + (u & 7) * 4);
        }
    };
    auto convertX = [&](int c) {
        const char* xs = sb + OFF_X + (uint32_t)(c & 1) * X_ST;
        const int r = tid >> 2, qd = tid & 3;
        const uint32_t xb = swz((uint32_t)(r * 128 + qd * 32));
        float4 v0 = *(const float4*)(xs + xb);
        float4 v1 = *(const float4*)(xs + (xb ^ 16));
        uint32_t h0, h1, h2, h3, l0, l1, l2, l3;
        h0 = packsplit(v0.x, v0.y, l0);  h1 = packsplit(v0.z, v0.w, l1);
        h2 = packsplit(v1.x, v1.y, l2);  h3 = packsplit(v1.z, v1.w, l3);
        const uint32_t ab = sbase + OFF_A + (uint32_t)(c & 1) * A_ST + (qd >> 1) * 8192
                          + (swz32((uint32_t)(r * 32)) ^ (uint32_t)((qd & 1) * 16));
        sts_u4(ab,      h0, h1, h2, h3);
        sts_u4(ab + SL, l0, l1, l2, l3);
    };

    // ---- prologue ----
    prefX(0);
    prefX(1);
    prefB(0);
    CP_COMMIT();
    CP_WAIT0();
    __syncthreads();
    convertX(0);

    float acc[2][4][4];
#pragma unroll
    for (int i = 0; i < 2; ++i)
#pragma unroll
        for (int j = 0; j < 4; ++j)
#pragma unroll
            for (int k = 0; k < 4; ++k) acc[i][j][k] = 0.0f;

    // ---- main loop (race-free schedule, as R9-R11) ----
#pragma unroll 1
    for (int c = 0; c < NCHUNK; ++c) {
        CP_WAIT0();
        __syncthreads();
        if (c + 2 < NCHUNK) prefX(c + 2);
        if (c + 1 < NCHUNK) prefB(c + 1);
        CP_COMMIT();

        const uint32_t Ast = sbase + OFF_A + (uint32_t)(c & 1) * A_ST;
        const uint32_t Bst = sbase + OFF_B + (uint32_t)(c & 1) * B_ST;
#pragma unroll
        for (int s = 0; s < 2; ++s) {
            const uint32_t ab = Ast + s * 8192 + aoff;
            const uint32_t bb = Bst + s * 8192 + boff;
            uint32_t ah[2][4], al[2][4], bq[2][4];
            LDSM4(ah[0], ab);
            LDSM4(ah[1], ab + 512);
            LDSM4(al[0], ab + SL);
            LDSM4(al[1], ab + SL + 512);
            LDSM4(bq[0], bb);
            LDSM4(bq[1], bb + 512);
#pragma unroll
            for (int mt = 0; mt < 2; ++mt)
#pragma unroll
                for (int p = 0; p < 2; ++p) {
                    mma_bf16(acc[mt][2*p],   ah[mt], bq[p][0], bq[p][1]);
                    mma_bf16(acc[mt][2*p+1], ah[mt], bq[p][2], bq[p][3]);
                }
#pragma unroll
            for (int mt = 0; mt < 2; ++mt)
#pragma unroll
                for (int p = 0; p < 2; ++p) {
                    mma_bf16(acc[mt][2*p],   al[mt], bq[p][0], bq[p][1]);
                    mma_bf16(acc[mt][2*p+1], al[mt], bq[p][2], bq[p][3]);
                }
            LDSM4(bq[0], bb + SL);
            LDSM4(bq[1], bb + SL + 512);
#pragma unroll
            for (int mt = 0; mt < 2; ++mt)
#pragma unroll
                for (int p = 0; p < 2; ++p) {
                    mma_bf16(acc[mt][2*p],   ah[mt], bq[p][0], bq[p][1]);
                    mma_bf16(acc[mt][2*p+1], ah[mt], bq[p][2], bq[p][3]);
                }
            if (s == 0 && c + 1 < NCHUNK) convertX(c + 1);
        }
    }
    __syncthreads();

    // ---- wait for omega CTAs (release/acquire; zero spins in practice) ----
    if (tid == 0) {
        int v;
        do {
            asm volatile("ld.acquire.gpu.global.b32 %0, [%1];" : "=r"(v) : "l"(&g_flag));
        } while (v < OMEGA_CTAS);
    }
    __syncthreads();

    // ---- epilogue: sin(omega*(acc+bias)) -> SMEM -> coalesced STG ----
    float* stg = (float*)sb;
#pragma unroll
    for (int mt = 0; mt < 2; ++mt) {
        int r0 = warpM + mt * 16 + lr;
        float o0 = __ldg(g_omega + gRow0 + r0);
        float o1 = __ldg(g_omega + gRow0 + r0 + 8);
#pragma unroll
        for (int nt = 0; nt < 4; ++nt) {
            int c0 = warpN + nt * 8 + lc;
            float b0 = __ldg(bias + gCol0 + c0), b1 = __ldg(bias + gCol0 + c0 + 1);
            float* a = acc[mt][nt];
            *(float2*)(stg + r0 * EPI_STRIDE + c0) =
                make_float2(__sinf(o0 * (a[0] + b0)), __sinf(o0 * (a[1] + b1)));
            *(float2*)(stg + (r0 + 8) * EPI_STRIDE + c0) =
                make_float2(__sinf(o1 * (a[2] + b0)), __sinf(o1 * (a[3] + b1)));
        }
    }
    __syncthreads();
#pragma unroll
    for (int i = 0; i < 8; ++i) {
        int lin = tid + i * NTHREADS;
        int rr = lin >> 5, c4 = (lin & 31) * 4;
        *(float4*)(out + (size_t)(gRow0 + rr) * ODIM + gCol0 + c4) =
            *(const float4*)(stg + rr * EPI_STRIDE + c4);
    }
}

// ---------------------------------------------------------------- launch
extern "C" void kernel_launch(void* const* d_in, const int* in_sizes, int n_in,
                              void* d_out, int out_size)
{
    const float* x     = (const float*)d_in[0];
    const float* q     = (const float*)d_in[1];
    const float* atoms = (const float*)d_in[2];
    const float* W     = (const float*)d_in[3];
    const float* bias  = (const float*)d_in[4];
    const float* fw1   = (const float*)d_in[5];
    const float* fb1   = (const float*)d_in[6];
    const float* fw2   = (const float*)d_in[7];
    const float* fb2   = (const float*)d_in[8];
    float* out = (float*)d_out;
    (void)in_sizes; (void)n_in; (void)out_size;

    cudaFuncSetAttribute(siren_main, cudaFuncAttributeMaxDynamicSharedMemorySize, SM_BYTES);

    prep_w<<<(ODIM * KDIM) / 256, 256>>>(W);
    siren_main<<<OMEGA_CTAS + GEMM_CTAS, NTHREADS, SM_BYTES>>>(
        x, q, atoms, bias, fw1, fb1, fw2, fb2, out);
}